// round 14
// baseline (speedup 1.0000x reference)
#include <cuda_runtime.h>
#include <cstdint>

#define N_NODES 500000
#define N_EDGES 1000000
#define EMB 64
#define FDIM 128
#define LDIM 8
#define OPC 5000

#define TILE 64

// ---- scratch (no allocations allowed) ----
__device__ uint16_t g_zh [(size_t)N_NODES * FDIM];   // z in bf16 (128 MB)
__device__ uint16_t g_agg[(size_t)N_NODES * FDIM];   // agg in bf16 (128 MB)
__device__ double   g_kl_sum;
__device__ double   g_lat_sum;

// ---- pre-packed weights/embeddings (bf16) ----
__device__ uint32_t g_pW1[128 * 128];
__device__ uint32_t g_pW2[64 * 256];
__device__ uint32_t g_pWd[128 * 128];
__device__ uint32_t g_pWh[64 * 16];
__device__ uint16_t g_pOpE[OPC * EMB];
__device__ uint16_t g_pSvE[2000 * EMB];
__device__ uint16_t g_pStE[16 * EMB];

// ---- helpers ----
__device__ __forceinline__ uint32_t smem_u32(const void* p) {
    uint32_t a;
    asm("{ .reg .u64 t; cvta.to.shared.u64 t, %1; cvt.u32.u64 %0, t; }"
        : "=r"(a) : "l"(p));
    return a;
}
__device__ __forceinline__ void ldsm_x4(uint32_t& r0, uint32_t& r1,
                                        uint32_t& r2, uint32_t& r3,
                                        uint32_t addr) {
    asm volatile("ldmatrix.sync.aligned.m8n8.x4.shared.b16 {%0,%1,%2,%3}, [%4];"
                 : "=r"(r0), "=r"(r1), "=r"(r2), "=r"(r3) : "r"(addr));
}
__device__ __forceinline__ void mma_bf16(float* d, const uint32_t* a,
                                         uint32_t b0, uint32_t b1) {
    asm volatile("mma.sync.aligned.m16n8k16.row.col.f32.bf16.bf16.f32 "
                 "{%0,%1,%2,%3}, {%4,%5,%6,%7}, {%8,%9}, {%0,%1,%2,%3};"
                 : "+f"(d[0]), "+f"(d[1]), "+f"(d[2]), "+f"(d[3])
                 : "r"(a[0]), "r"(a[1]), "r"(a[2]), "r"(a[3]),
                   "r"(b0), "r"(b1));
}
__device__ __forceinline__ uint32_t bf2(float lo, float hi) {
    uint32_t d;
    asm("cvt.rn.satfinite.bf16x2.f32 %0, %1, %2;" : "=r"(d) : "f"(hi), "f"(lo));
    return d;
}
__device__ __forceinline__ void cpa16(uint32_t dst, const void* src) {
    asm volatile("cp.async.cg.shared.global [%0], [%1], 16;"
                 :: "r"(dst), "l"(src) : "memory");
}
#define CP_COMMIT() asm volatile("cp.async.commit_group;" ::: "memory")
#define CP_WAIT(n)  asm volatile("cp.async.wait_group %0;" :: "n"(n) : "memory")

// fast transcendentals (HW approx)
__device__ __forceinline__ float fexp(float x) {
    float r;
    asm("ex2.approx.f32 %0, %1;" : "=f"(r) : "f"(x * 1.4426950408889634f));
    return r;
}
__device__ __forceinline__ float ftanh(float x) {
    float r;
    asm("tanh.approx.f32 %0, %1;" : "=f"(r) : "f"(x));
    return r;
}

// ----------------------------------------------------------------------------
// Kernel 0: zero agg + out + scalars, AND pack weights/embeddings
// ----------------------------------------------------------------------------
__global__ void zero_prep_kernel(float* __restrict__ out,
                                 const float* __restrict__ W1,
                                 const float* __restrict__ W2,
                                 const float* __restrict__ Wself,
                                 const float* __restrict__ Wagg,
                                 const float* __restrict__ muW,
                                 const float* __restrict__ lvW,
                                 const float* __restrict__ opE,
                                 const float* __restrict__ svE,
                                 const float* __restrict__ stE)
{
    const size_t i = (size_t)blockIdx.x * blockDim.x + threadIdx.x;
    const size_t tot8 = (size_t)N_NODES * FDIM / 8;
    if (i < tot8) ((uint4*)g_agg)[i] = make_uint4(0u, 0u, 0u, 0u);
    if (i < (size_t)(1 + 2*OPC)) out[i] = 0.f;
    if (i == 0) { g_kl_sum = 0.0; g_lat_sum = 0.0; }

    if (i < 16384) {
        const int kp = (int)i >> 7, n = (int)i & 127;
        const int k0 = 2 * kp;
        const float lo = (k0 < 200)     ? __ldg(W1 + (size_t)k0 * FDIM + n)     : 0.f;
        const float hi = (k0 + 1 < 200) ? __ldg(W1 + (size_t)(k0+1) * FDIM + n) : 0.f;
        g_pW1[i] = bf2(lo, hi);
    } else if (i < 32768) {
        const int j = (int)i - 16384;
        const int kp = j >> 8, n = j & 255;
        const int k0 = 2 * kp;
        g_pW2[j] = bf2(__ldg(W2 + (size_t)k0 * 256 + n),
                       __ldg(W2 + (size_t)(k0+1) * 256 + n));
    } else if (i < 49152) {
        const int j = (int)i - 32768;
        const int kp = j >> 7, n = j & 127;
        const float* src = (kp < 64) ? Wself : Wagg;
        const int k0 = (kp < 64) ? 2*kp : 2*(kp - 64);
        g_pWd[j] = bf2(__ldg(src + (size_t)k0 * FDIM + n),
                       __ldg(src + (size_t)(k0+1) * FDIM + n));
    } else if (i < 50176) {
        const int j = (int)i - 49152;
        const int kp = j >> 4, nn = j & 15;
        float lo, hi;
        if (nn < 8) {
            lo = __ldg(muW + (size_t)(2*kp) * LDIM + nn);
            hi = __ldg(muW + (size_t)(2*kp+1) * LDIM + nn);
        } else {
            lo = __ldg(lvW + (size_t)(2*kp) * LDIM + nn - 8);
            hi = __ldg(lvW + (size_t)(2*kp+1) * LDIM + nn - 8);
        }
        g_pWh[j] = bf2(lo, hi);
    } else if (i < 210176) {
        const int j = (int)i - 50176;
        const float2 v = __ldg((const float2*)(opE + 2*(size_t)j));
        ((uint32_t*)g_pOpE)[j] = bf2(v.x, v.y);
    } else if (i < 274176) {
        const int j = (int)i - 210176;
        const float2 v = __ldg((const float2*)(svE + 2*(size_t)j));
        ((uint32_t*)g_pSvE)[j] = bf2(v.x, v.y);
    } else if (i < 274688) {
        const int j = (int)i - 274176;
        const float2 v = __ldg((const float2*)(stE + 2*(size_t)j));
        ((uint32_t*)g_pStE)[j] = bf2(v.x, v.y);
    }
}

// ----------------------------------------------------------------------------
// Kernel 1: encoder, occ-3 variant.
//   smem (69.5 KB): X1 bf16[64][216] @0 | WpA u32[24][136] @27648 |
//                   WpB @40704 | Hs bf16[64][136] @53760
//   GEMM1: K=208 = 13 k-steps, chunks of 3 (5 chunks), double-buffered.
//   GEMM2: B operands via __ldg from g_pW2 (L1-resident, no smem staging).
// ----------------------------------------------------------------------------
extern "C" __global__ void __launch_bounds__(256, 3)
enc_kernel(const int*   __restrict__ op_id,
           const int*   __restrict__ sv_id,
           const int*   __restrict__ st_id,
           const float* __restrict__ lat,
           const float* __restrict__ eps,
           const float* __restrict__ b1,
           const float* __restrict__ b2)
{
    extern __shared__ __align__(16) char smraw[];
    uint16_t* X1 = (uint16_t*)smraw;                // [64][216]
    uint16_t* Hs = (uint16_t*)(smraw + 53760);      // [64][136]
    __shared__ float skl[8];

    const int tid  = threadIdx.x;
    const int lane = tid & 31;
    const int w    = tid >> 5;
    const int base = blockIdx.x * TILE;
    const int g    = lane >> 2;
    const int t    = lane & 3;
    const uint32_t x1b  = smem_u32(X1);
    const uint32_t hsb  = smem_u32(Hs);
    const uint32_t wb[2] = { smem_u32(smraw + 27648), smem_u32(smraw + 40704) };

    // stage 24-kpair chunk (3 k-steps): 24 x 32 uint4 = 768 units, 3/thread
    auto stage1 = [&](int ch, uint32_t wbuf) {
        #pragma unroll
        for (int i = 0; i < 3; i++) {
            const int idx = tid + i*256;            // 768 = 24 kp x 32 u4
            const int kp_l = idx >> 5, n4 = (idx & 31) << 2;
            cpa16(wbuf + (kp_l*136 + n4)*4,
                  g_pW1 + (size_t)(ch*24 + kp_l)*FDIM + n4);   // kp<=119<128: safe
        }
    };

    // ---- prologue ----
    stage1(0, wb[0]);
    CP_COMMIT();
    {
        const int r = tid >> 2, q = tid & 3;
        const int n = base + r;
        uint16_t* row = X1 + r * 216;
        if (n < N_NODES) {
            const int op = op_id[n], sv = sv_id[n], st = st_id[n];
            const uint4* so = (const uint4*)(g_pOpE + (size_t)op*EMB + q*16);
            const uint4* ss = (const uint4*)(g_pSvE + (size_t)sv*EMB + q*16);
            const uint4* st4 = (const uint4*)(g_pStE + (size_t)st*EMB + q*16);
            *(uint4*)(row + q*16)          = __ldg(so);
            *(uint4*)(row + q*16 + 8)      = __ldg(so + 1);
            *(uint4*)(row + 64 + q*16)     = __ldg(ss);
            *(uint4*)(row + 64 + q*16 + 8) = __ldg(ss + 1);
            *(uint4*)(row + 128 + q*16)    = __ldg(st4);
            *(uint4*)(row + 128 + q*16 + 8)= __ldg(st4 + 1);
            if (q == 0) {
                const float4 v0 = __ldg((const float4*)(lat + (size_t)n*LDIM));
                const float4 v1 = __ldg((const float4*)(lat + (size_t)n*LDIM + 4));
                *(uint4*)(row + 192) = make_uint4(bf2(v0.x,v0.y), bf2(v0.z,v0.w),
                                                  bf2(v1.x,v1.y), bf2(v1.z,v1.w));
            } else if (q == 1) {
                *(uint4*)(row + 200) = make_uint4(0u,0u,0u,0u);
            }
        } else {
            const uint4 z4 = make_uint4(0u,0u,0u,0u);
            *(uint4*)(row + q*16)           = z4;
            *(uint4*)(row + q*16 + 8)       = z4;
            *(uint4*)(row + 64 + q*16)      = z4;
            *(uint4*)(row + 64 + q*16 + 8)  = z4;
            *(uint4*)(row + 128 + q*16)     = z4;
            *(uint4*)(row + 128 + q*16 + 8) = z4;
            if (q == 0)      *(uint4*)(row + 192) = z4;
            else if (q == 1) *(uint4*)(row + 200) = z4;
        }
    }
    stage1(1, wb[1]);
    CP_COMMIT();
    CP_WAIT(1);
    __syncthreads();

    // ---- GEMM1: h = relu(X1 @ W1 + b1), 13 k-steps, 5 chunks of 3 ----
    float acc1[2][4][4];
    #pragma unroll
    for (int i = 0; i < 2; i++)
        #pragma unroll
        for (int nt = 0; nt < 4; nt++)
            #pragma unroll
            for (int j = 0; j < 4; j++) acc1[i][nt][j] = 0.f;

    const int mp  = w & 1;
    const int nq1 = w >> 1;

    for (int ch = 0; ch < 5; ch++) {
        const uint32_t* Wc = (const uint32_t*)(smraw + ((ch & 1) ? 40704 : 27648));
        const int nsteps = (ch < 4) ? 3 : 1;
        for (int ls = 0; ls < nsteps; ls++) {
            const int koff = ls << 3;
            const int kidx = ch*48 + (ls << 4);
            uint32_t a0[4], a1[4];
            const uint32_t addr = x1b + (mp*32 + (lane & 15)) * 432
                                + ((kidx + ((lane >> 4) << 3)) << 1);
            ldsm_x4(a0[0], a0[1], a0[2], a0[3], addr);
            ldsm_x4(a1[0], a1[1], a1[2], a1[3], addr + 16*432);
            #pragma unroll
            for (int nt = 0; nt < 4; nt++) {
                const int ncol = nq1*32 + nt*8 + g;
                const uint32_t b0 = Wc[(koff + t)*136 + ncol];
                const uint32_t bv = Wc[(koff + 4 + t)*136 + ncol];
                mma_bf16(acc1[0][nt], a0, b0, bv);
                mma_bf16(acc1[1][nt], a1, b0, bv);
            }
        }
        if (ch < 4) {
            __syncthreads();
            if (ch + 2 < 5) {
                stage1(ch + 2, wb[ch & 1]);
                CP_COMMIT();
                CP_WAIT(1);
            } else {
                CP_WAIT(0);
            }
            __syncthreads();
        }
    }

    // ---- h = relu(+bias) -> Hs bf16 ----
    #pragma unroll
    for (int i = 0; i < 2; i++)
        #pragma unroll
        for (int nt = 0; nt < 4; nt++) {
            const int r = mp*32 + i*16 + g;
            const int c = nq1*32 + nt*8 + 2*t;
            const float bA = __ldg(b1 + c), bB = __ldg(b1 + c + 1);
            ((uint32_t*)Hs)[r*68 + (c>>1)] =
                bf2(fmaxf(acc1[i][nt][0] + bA, 0.f), fmaxf(acc1[i][nt][1] + bB, 0.f));
            ((uint32_t*)Hs)[(r+8)*68 + (c>>1)] =
                bf2(fmaxf(acc1[i][nt][2] + bA, 0.f), fmaxf(acc1[i][nt][3] + bB, 0.f));
        }
    __syncthreads();

    // ---- GEMM2: y = h @ W2, K=128, B straight from L1 (__ldg) ----
    float acc2[4][4][4];
    #pragma unroll
    for (int mi = 0; mi < 4; mi++)
        #pragma unroll
        for (int j = 0; j < 4; j++)
            #pragma unroll
            for (int e = 0; e < 4; e++) acc2[mi][j][e] = 0.f;

    for (int s = 0; s < 8; s++) {
        const int koff = s << 3;
        const int kidx = s << 4;
        uint32_t a[4][4];
        #pragma unroll
        for (int mi = 0; mi < 4; mi++) {
            const uint32_t addr = hsb + (mi*16 + (lane & 15)) * 272
                                + ((kidx + ((lane >> 4) << 3)) << 1);
            ldsm_x4(a[mi][0], a[mi][1], a[mi][2], a[mi][3], addr);
        }
        #pragma unroll
        for (int j = 0; j < 4; j++) {
            const int cb = (j < 2) ? (w*16 + 8*j) : (FDIM + w*16 + 8*(j-2));
            const uint32_t b0 = __ldg(g_pW2 + (size_t)(koff + t)*256 + cb + g);
            const uint32_t bv = __ldg(g_pW2 + (size_t)(koff + 4 + t)*256 + cb + g);
            #pragma unroll
            for (int mi = 0; mi < 4; mi++)
                mma_bf16(acc2[mi][j], a[mi], b0, bv);
        }
    }

    // ---- epilogue: z = mu + exp(0.5*tanh(lv))*eps -> g_zh, KL ----
    float klw = 0.f;
    #pragma unroll
    for (int j = 0; j < 2; j++) {
        const int c = w*16 + 8*j + 2*t;
        const float bmx = __ldg(b2 + c),        bmy = __ldg(b2 + c + 1);
        const float blx = __ldg(b2 + FDIM + c), bly = __ldg(b2 + FDIM + c + 1);
        #pragma unroll
        for (int mi = 0; mi < 4; mi++) {
            const float* fm = acc2[mi][j];
            const float* fl = acc2[mi][j+2];
            #pragma unroll
            for (int half = 0; half < 2; half++) {
                const int r = mi*16 + g + half*8;
                const int n = base + r;
                if (n < N_NODES) {
                    const float mux = fm[2*half]   + bmx;
                    const float muy = fm[2*half+1] + bmy;
                    const float lvx = ftanh(fl[2*half]   + blx);
                    const float lvy = ftanh(fl[2*half+1] + bly);
                    const float2 e = __ldg((const float2*)(eps + (size_t)n*FDIM + c));
                    const float zx = mux + fexp(0.5f*lvx) * e.x;
                    const float zy = muy + fexp(0.5f*lvy) * e.y;
                    ((uint32_t*)g_zh)[(size_t)n*64 + (c>>1)] = bf2(zx, zy);
                    klw += lvx + 1.f - fexp(lvx) - mux*mux;
                    klw += lvy + 1.f - fexp(lvy) - muy*muy;
                }
            }
        }
    }
    #pragma unroll
    for (int o = 16; o; o >>= 1) klw += __shfl_xor_sync(0xffffffffu, klw, o);
    if (lane == 0) skl[w] = klw;
    __syncthreads();
    if (tid == 0) {
        double s = 0.0;
        #pragma unroll
        for (int i = 0; i < 8; i++) s += (double)skl[i];
        atomicAdd(&g_kl_sum, s);
    }
}

// ----------------------------------------------------------------------------
// Kernel 2: edge scatter-add — 8 edges/warp, 16B slices, MLP-4 unroll
// ----------------------------------------------------------------------------
__global__ void scatter_kernel(const int* __restrict__ esrc,
                               const int* __restrict__ edst)
{
    const int warp = (blockIdx.x * blockDim.x + threadIdx.x) >> 5;
    const int lane = threadIdx.x & 31;
    const int sub  = lane >> 4;
    const int off  = lane & 15;
    const int ebase = warp * 8 + sub;

    int   s[4], d[4];
    uint4 v[4];
    #pragma unroll
    for (int i = 0; i < 4; i++) {
        const int e = ebase + 2*i;
        s[i] = (e < N_EDGES) ? __ldg(esrc + e) : 0;
        d[i] = (e < N_EDGES) ? __ldg(edst + e) : 0;
    }
    #pragma unroll
    for (int i = 0; i < 4; i++)
        v[i] = __ldg((const uint4*)(g_zh + (size_t)s[i] * FDIM) + off);
    #pragma unroll
    for (int i = 0; i < 4; i++) {
        const int e = ebase + 2*i;
        if (e < N_EDGES) {
            uint32_t* p = (uint32_t*)(g_agg + (size_t)d[i] * FDIM) + 4*off;
            asm volatile("red.global.add.noftz.v4.bf16x2 [%0], {%1, %2, %3, %4};"
                         :: "l"(p), "r"(v[i].x), "r"(v[i].y), "r"(v[i].z), "r"(v[i].w)
                         : "memory");
        }
    }
}

// ----------------------------------------------------------------------------
// Kernel 3: decoder (R13 config, unchanged: 32-kpair chunks, occ 3)
// ----------------------------------------------------------------------------
extern "C" __global__ void __launch_bounds__(256, 3)
dec_kernel(const int*   __restrict__ op_id,
           const float* __restrict__ lat,
           const float* __restrict__ mub,
           const float* __restrict__ lvb,
           const float* __restrict__ opw,
           float* __restrict__ op_loss,
           float* __restrict__ op_cnt)
{
    extern __shared__ __align__(16) char smraw[];
    uint16_t* X   = (uint16_t*)smraw;               // [64][264]
    uint16_t* Yd  = (uint16_t*)smraw;               // [64][136] (post-GEMM)
    uint32_t* Whp = (uint32_t*)(smraw + 17408);     // [64][24]
    float*    Yh  = (float*)(smraw + 23552);        // [64][20]
    __shared__ float sL[8];

    const int tid  = threadIdx.x;
    const int lane = tid & 31;
    const int w    = tid >> 5;
    const int base = blockIdx.x * TILE;
    const int g    = lane >> 2;
    const int t    = lane & 3;
    const uint32_t xb  = smem_u32(X);
    const uint32_t ydb = smem_u32(Yd);
    const uint32_t wbuf[2] = { smem_u32(smraw + 33792), smem_u32(smraw + 51200) };

    auto staged = [&](int ch, uint32_t wdst) {
        #pragma unroll
        for (int i = 0; i < 4; i++) {
            const int idx = tid + i*256;
            const int kp_l = idx >> 5, n4 = (idx & 31) << 2;
            cpa16(wdst + (kp_l*136 + n4)*4,
                  g_pWd + (size_t)(ch*32 + kp_l)*FDIM + n4);
        }
    };

    staged(0, wbuf[0]);
    CP_COMMIT();
    #pragma unroll
    for (int it = 0; it < 8; it++) {
        const int u = tid + it*256;
        const int r = u >> 5, half = (u >> 4) & 1, seg = u & 15;
        const int n = base + r;
        const uint32_t dst = xb + (r*264 + half*128 + seg*8) * 2;
        if (n < N_NODES) {
            const uint16_t* src = (half ? g_agg : g_zh) + (size_t)n*FDIM + seg*8;
            cpa16(dst, src);
        } else {
            *(uint4*)((char*)X + (dst - xb)) = make_uint4(0u,0u,0u,0u);
        }
    }
    CP_COMMIT();
    staged(1, wbuf[1]);
    CP_COMMIT();
    CP_WAIT(1);
    __syncthreads();

    float acc[2][4][4];
    #pragma unroll
    for (int i = 0; i < 2; i++)
        #pragma unroll
        for (int nt = 0; nt < 4; nt++)
            #pragma unroll
            for (int e = 0; e < 4; e++) acc[i][nt][e] = 0.f;

    const int mp  = w & 1;
    const int nqd = w >> 1;

    for (int ch = 0; ch < 4; ch++) {
        const uint32_t* Wc = (const uint32_t*)(smraw + ((ch & 1) ? 51200 : 33792));
        for (int s = 0; s < 4; s++) {
            const int koff = s << 3;
            const int kidx = ch*64 + (s << 4);
            uint32_t a0[4], a1[4];
            const uint32_t addr = xb + (mp*32 + (lane & 15)) * 528
                                + ((kidx + ((lane >> 4) << 3)) << 1);
            ldsm_x4(a0[0], a0[1], a0[2], a0[3], addr);
            ldsm_x4(a1[0], a1[1], a1[2], a1[3], addr + 16*528);
            #pragma unroll
            for (int nt = 0; nt < 4; nt++) {
                const int ncol = nqd*32 + nt*8 + g;
                const uint32_t b0 = Wc[(koff + t)*136 + ncol];
                const uint32_t bv = Wc[(koff + 4 + t)*136 + ncol];
                mma_bf16(acc[0][nt], a0, b0, bv);
                mma_bf16(acc[1][nt], a1, b0, bv);
            }
        }
        if (ch < 3) {
            __syncthreads();
            if (ch + 2 < 4) {
                staged(ch + 2, wbuf[ch & 1]);
                CP_COMMIT();
                CP_WAIT(1);
            } else {
                CP_WAIT(0);
            }
            __syncthreads();
        }
    }
    __syncthreads();

    #pragma unroll
    for (int i = 0; i < 2; i++)
        #pragma unroll
        for (int nt = 0; nt < 4; nt++) {
            const int r = mp*32 + i*16 + g;
            const int c = nqd*32 + nt*8 + 2*t;
            ((uint32_t*)Yd)[r*68 + (c>>1)] =
                bf2(fmaxf(acc[i][nt][0], 0.f), fmaxf(acc[i][nt][1], 0.f));
            ((uint32_t*)Yd)[(r+8)*68 + (c>>1)] =
                bf2(fmaxf(acc[i][nt][2], 0.f), fmaxf(acc[i][nt][3], 0.f));
        }
    #pragma unroll
    for (int i = 0; i < 4; i++) {
        const int idx = tid + i*256;
        const int kp = idx >> 4, nn = idx & 15;
        Whp[kp*24 + nn] = g_pWh[kp*16 + nn];
    }
    __syncthreads();

    {
        const int mt = w & 3;
        const int nh = (w >> 2) & 1;
        float ah[4] = {0.f, 0.f, 0.f, 0.f};
        for (int s = 0; s < 8; s++) {
            const int koff = s << 3;
            uint32_t a[4];
            const uint32_t addr = ydb + (mt*16 + (lane & 15)) * 272
                                + (((s << 4) + ((lane >> 4) << 3)) << 1);
            ldsm_x4(a[0], a[1], a[2], a[3], addr);
            const uint32_t b0 = Whp[(koff + t)*24 + nh*8 + g];
            const uint32_t bv = Whp[(koff + 4 + t)*24 + nh*8 + g];
            mma_bf16(ah, a, b0, bv);
        }
        const int r = mt*16 + g;
        const int c = nh*8 + 2*t;
        const float* bp = nh ? lvb : mub;
        const float bx = __ldg(bp + 2*t), by = __ldg(bp + 2*t + 1);
        Yh[r*20 + c]         = ah[0] + bx;
        Yh[r*20 + c + 1]     = ah[1] + by;
        Yh[(r+8)*20 + c]     = ah[2] + bx;
        Yh[(r+8)*20 + c + 1] = ah[3] + by;
    }
    __syncthreads();

    {
        const int r  = tid >> 2;
        const int kg = tid & 3;
        const int n  = base + r;
        const bool valid = (n < N_NODES);
        float part = 0.f;
        int op = 0;
        if (valid) {
            op = __ldg(op_id + n);
            const float4 muA = *(const float4*)(Yh + r*20);
            const float4 muB = *(const float4*)(Yh + r*20 + 4);
            const float4 lvA = *(const float4*)(Yh + r*20 + 8);
            const float4 lvB = *(const float4*)(Yh + r*20 + 12);
            const float muv[8] = { muA.x, muA.y, muA.z, muA.w, muB.x, muB.y, muB.z, muB.w };
            const float lvv[8] = { lvA.x, lvA.y, lvA.z, lvA.w, lvB.x, lvB.y, lvB.z, lvB.w };
            const float* wrow = opw + (size_t)op * (2 * LDIM * LDIM);
            float mpA = 0.f, mpB = 0.f, lpA = 0.f, lpB = 0.f;
            #pragma unroll
            for (int l = 0; l < LDIM; l++) {
                const float2 wm = __ldg((const float2*)(wrow + l*2*LDIM + 2*kg));
                const float2 wl = __ldg((const float2*)(wrow + l*2*LDIM + LDIM + 2*kg));
                mpA += muv[l] * wm.x; mpB += muv[l] * wm.y;
                lpA += lvv[l] * wl.x; lpB += lvv[l] * wl.y;
            }
            const float2 lab = __ldg((const float2*)(lat + (size_t)n*LDIM + 2*kg));
            const float dA = mpA - lab.x, dB = mpB - lab.y;
            part = dA*dA / (2.f*fexp(lpA) + 1e-7f) + 0.5f*lpA
                 + dB*dB / (2.f*fexp(lpB) + 1e-7f) + 0.5f*lpB;
        }
        part += __shfl_xor_sync(0xffffffffu, part, 1);
        part += __shfl_xor_sync(0xffffffffu, part, 2);
        const float lossn = part * (1.f / LDIM);
        if (valid && kg == 0) {
            atomicAdd(op_loss + op, lossn);
            atomicAdd(op_cnt  + op, 1.f);
        }
        float wval = (valid && kg == 0) ? lossn : 0.f;
        wval += __shfl_xor_sync(0xffffffffu, wval, 4);
        wval += __shfl_xor_sync(0xffffffffu, wval, 8);
        wval += __shfl_xor_sync(0xffffffffu, wval, 16);
        if (lane == 0) sL[w] = wval;
    }
    __syncthreads();
    if (tid == 0) {
        double s = 0.0;
        #pragma unroll
        for (int i = 0; i < 8; i++) s += (double)sL[i];
        atomicAdd(&g_lat_sum, s);
    }
}

// ----------------------------------------------------------------------------
// Kernel 4: finalize
// ----------------------------------------------------------------------------
__global__ void fin_kernel(float* __restrict__ out)
{
    if (threadIdx.x == 0) {
        const double lat_loss = g_lat_sum / (double)N_NODES;
        const double kl = -0.5 * (g_kl_sum / ((double)N_NODES * (double)FDIM));
        out[0] = (float)(lat_loss + kl);
    }
}

// ----------------------------------------------------------------------------
extern "C" void kernel_launch(void* const* d_in, const int* in_sizes, int n_in,
                              void* d_out, int out_size)
{
    const int*   op_id = (const int*)  d_in[0];
    const int*   sv_id = (const int*)  d_in[1];
    const int*   st_id = (const int*)  d_in[2];
    const float* lat   = (const float*)d_in[3];
    const int*   esrc  = (const int*)  d_in[4];
    const int*   edst  = (const int*)  d_in[5];
    const float* eps   = (const float*)d_in[6];
    const float* opE   = (const float*)d_in[7];
    const float* svE   = (const float*)d_in[8];
    const float* stE   = (const float*)d_in[9];
    const float* W1    = (const float*)d_in[10];
    const float* b1    = (const float*)d_in[11];
    const float* W2    = (const float*)d_in[12];
    const float* b2    = (const float*)d_in[13];
    const float* Wself = (const float*)d_in[14];
    const float* Wagg  = (const float*)d_in[15];
    const float* muW   = (const float*)d_in[16];
    const float* mub   = (const float*)d_in[17];
    const float* lvW   = (const float*)d_in[18];
    const float* lvb   = (const float*)d_in[19];
    const float* opw   = (const float*)d_in[20];

    float* out     = (float*)d_out;
    float* op_loss = out + 1;
    float* op_cnt  = out + 1 + OPC;

    const int ENC_SMEM = 71168;
    const int DEC_SMEM = 68608;
    static bool attr_done = false;
    if (!attr_done) {
        cudaFuncSetAttribute(enc_kernel, cudaFuncAttributeMaxDynamicSharedMemorySize, ENC_SMEM);
        cudaFuncSetAttribute(dec_kernel, cudaFuncAttributeMaxDynamicSharedMemorySize, DEC_SMEM);
        attr_done = true;
    }

    const int n_tiles = (N_NODES + TILE - 1) / TILE;   // 7813

    zero_prep_kernel<<<31250, 256>>>(out, W1, W2, Wself, Wagg, muW, lvW,
                                     opE, svE, stE);

    enc_kernel<<<n_tiles, 256, ENC_SMEM>>>(op_id, sv_id, st_id, lat, eps, b1, b2);

    scatter_kernel<<<15625, 256>>>(esrc, edst);

    dec_kernel<<<n_tiles, 256, DEC_SMEM>>>(op_id, lat, mub, lvb, opw,
                                           op_loss, op_cnt);

    fin_kernel<<<1, 32>>>(out);
}

// round 15
// speedup vs baseline: 1.0742x; 1.0742x over previous
#include <cuda_runtime.h>
#include <cstdint>

#define N_NODES 500000
#define N_EDGES 1000000
#define EMB 64
#define FDIM 128
#define LDIM 8
#define OPC 5000

#define TILE 64

// ---- scratch (no allocations allowed) ----
__device__ uint16_t g_zh [(size_t)N_NODES * FDIM];   // z in bf16 (128 MB)
__device__ uint16_t g_agg[(size_t)N_NODES * FDIM];   // agg in bf16 (128 MB)
__device__ double   g_kl_sum;
__device__ double   g_lat_sum;

// ---- pre-packed weights/embeddings (bf16) ----
__device__ uint32_t g_pW1[128 * 128];
__device__ uint32_t g_pW2[64 * 256];
__device__ uint32_t g_pWd[128 * 128];
__device__ uint32_t g_pWh[64 * 16];
__device__ uint16_t g_pOpE[OPC * EMB];
__device__ uint16_t g_pSvE[2000 * EMB];
__device__ uint16_t g_pStE[16 * EMB];

// ---- helpers ----
__device__ __forceinline__ uint32_t smem_u32(const void* p) {
    uint32_t a;
    asm("{ .reg .u64 t; cvta.to.shared.u64 t, %1; cvt.u32.u64 %0, t; }"
        : "=r"(a) : "l"(p));
    return a;
}
__device__ __forceinline__ void ldsm_x4(uint32_t& r0, uint32_t& r1,
                                        uint32_t& r2, uint32_t& r3,
                                        uint32_t addr) {
    asm volatile("ldmatrix.sync.aligned.m8n8.x4.shared.b16 {%0,%1,%2,%3}, [%4];"
                 : "=r"(r0), "=r"(r1), "=r"(r2), "=r"(r3) : "r"(addr));
}
__device__ __forceinline__ void mma_bf16(float* d, const uint32_t* a,
                                         uint32_t b0, uint32_t b1) {
    asm volatile("mma.sync.aligned.m16n8k16.row.col.f32.bf16.bf16.f32 "
                 "{%0,%1,%2,%3}, {%4,%5,%6,%7}, {%8,%9}, {%0,%1,%2,%3};"
                 : "+f"(d[0]), "+f"(d[1]), "+f"(d[2]), "+f"(d[3])
                 : "r"(a[0]), "r"(a[1]), "r"(a[2]), "r"(a[3]),
                   "r"(b0), "r"(b1));
}
__device__ __forceinline__ uint32_t bf2(float lo, float hi) {
    uint32_t d;
    asm("cvt.rn.satfinite.bf16x2.f32 %0, %1, %2;" : "=r"(d) : "f"(hi), "f"(lo));
    return d;
}
__device__ __forceinline__ void cpa16(uint32_t dst, const void* src) {
    asm volatile("cp.async.cg.shared.global [%0], [%1], 16;"
                 :: "r"(dst), "l"(src) : "memory");
}
#define CP_COMMIT() asm volatile("cp.async.commit_group;" ::: "memory")
#define CP_WAIT(n)  asm volatile("cp.async.wait_group %0;" :: "n"(n) : "memory")

// fast transcendentals (HW approx; |err| far below the 1e-3 gate)
__device__ __forceinline__ float fexp(float x) {
    float r;
    asm("ex2.approx.f32 %0, %1;" : "=f"(r) : "f"(x * 1.4426950408889634f));
    return r;
}
__device__ __forceinline__ float ftanh(float x) {
    float r;
    asm("tanh.approx.f32 %0, %1;" : "=f"(r) : "f"(x));
    return r;
}

// ----------------------------------------------------------------------------
// Kernel 0: zero agg + out + scalars, AND pack weights/embeddings (fused prep)
// ----------------------------------------------------------------------------
__global__ void zero_prep_kernel(float* __restrict__ out,
                                 const float* __restrict__ W1,
                                 const float* __restrict__ W2,
                                 const float* __restrict__ Wself,
                                 const float* __restrict__ Wagg,
                                 const float* __restrict__ muW,
                                 const float* __restrict__ lvW,
                                 const float* __restrict__ opE,
                                 const float* __restrict__ svE,
                                 const float* __restrict__ stE)
{
    const size_t i = (size_t)blockIdx.x * blockDim.x + threadIdx.x;
    const size_t tot8 = (size_t)N_NODES * FDIM / 8;
    if (i < tot8) ((uint4*)g_agg)[i] = make_uint4(0u, 0u, 0u, 0u);
    if (i < (size_t)(1 + 2*OPC)) out[i] = 0.f;
    if (i == 0) { g_kl_sum = 0.0; g_lat_sum = 0.0; }

    if (i < 16384) {
        const int kp = (int)i >> 7, n = (int)i & 127;
        const int k0 = 2 * kp;
        const float lo = (k0 < 200)     ? __ldg(W1 + (size_t)k0 * FDIM + n)     : 0.f;
        const float hi = (k0 + 1 < 200) ? __ldg(W1 + (size_t)(k0+1) * FDIM + n) : 0.f;
        g_pW1[i] = bf2(lo, hi);
    } else if (i < 32768) {
        const int j = (int)i - 16384;
        const int kp = j >> 8, n = j & 255;
        const int k0 = 2 * kp;
        g_pW2[j] = bf2(__ldg(W2 + (size_t)k0 * 256 + n),
                       __ldg(W2 + (size_t)(k0+1) * 256 + n));
    } else if (i < 49152) {
        const int j = (int)i - 32768;
        const int kp = j >> 7, n = j & 127;
        const float* src = (kp < 64) ? Wself : Wagg;
        const int k0 = (kp < 64) ? 2*kp : 2*(kp - 64);
        g_pWd[j] = bf2(__ldg(src + (size_t)k0 * FDIM + n),
                       __ldg(src + (size_t)(k0+1) * FDIM + n));
    } else if (i < 50176) {
        const int j = (int)i - 49152;
        const int kp = j >> 4, nn = j & 15;
        float lo, hi;
        if (nn < 8) {
            lo = __ldg(muW + (size_t)(2*kp) * LDIM + nn);
            hi = __ldg(muW + (size_t)(2*kp+1) * LDIM + nn);
        } else {
            lo = __ldg(lvW + (size_t)(2*kp) * LDIM + nn - 8);
            hi = __ldg(lvW + (size_t)(2*kp+1) * LDIM + nn - 8);
        }
        g_pWh[j] = bf2(lo, hi);
    } else if (i < 210176) {
        const int j = (int)i - 50176;
        const float2 v = __ldg((const float2*)(opE + 2*(size_t)j));
        ((uint32_t*)g_pOpE)[j] = bf2(v.x, v.y);
    } else if (i < 274176) {
        const int j = (int)i - 210176;
        const float2 v = __ldg((const float2*)(svE + 2*(size_t)j));
        ((uint32_t*)g_pSvE)[j] = bf2(v.x, v.y);
    } else if (i < 274688) {
        const int j = (int)i - 274176;
        const float2 v = __ldg((const float2*)(stE + 2*(size_t)j));
        ((uint32_t*)g_pStE)[j] = bf2(v.x, v.y);
    }
}

// ----------------------------------------------------------------------------
// Kernel 1: encoder (bf16 mma), 64-node tile, 256 threads, cp.async pipeline
//   smem (85 KB): X1 bf16[64][216] @0 | WpA u32[32][136] @27648 | WpB @45056 |
//                 Hs bf16[64][136] @67584 ; phase2: Wp2 u32[64][264] @0
// ----------------------------------------------------------------------------
extern "C" __global__ void __launch_bounds__(256, 2)
enc_kernel(const int*   __restrict__ op_id,
           const int*   __restrict__ sv_id,
           const int*   __restrict__ st_id,
           const float* __restrict__ lat,
           const float* __restrict__ eps,
           const float* __restrict__ b1,
           const float* __restrict__ b2)
{
    extern __shared__ __align__(16) char smraw[];
    uint16_t* X1  = (uint16_t*)smraw;               // [64][216]
    uint16_t* Hs  = (uint16_t*)(smraw + 67584);     // [64][136]
    uint32_t* Wp2 = (uint32_t*)smraw;               // [64][264]
    __shared__ float skl[8];

    const int tid  = threadIdx.x;
    const int lane = tid & 31;
    const int w    = tid >> 5;
    const int base = blockIdx.x * TILE;
    const int g    = lane >> 2;
    const int t    = lane & 3;
    const uint32_t x1b  = smem_u32(X1);
    const uint32_t hsb  = smem_u32(Hs);
    const uint32_t wb[2] = { smem_u32(smraw + 27648), smem_u32(smraw + 45056) };

    auto stage1 = [&](int ch, uint32_t wbuf) {
        #pragma unroll
        for (int i = 0; i < 4; i++) {
            const int idx = tid + i*256;
            const int kp_l = idx >> 5, n4 = (idx & 31) << 2;
            cpa16(wbuf + (kp_l*136 + n4)*4,
                  g_pW1 + (size_t)(ch*32 + kp_l)*FDIM + n4);
        }
    };

    // ---- prologue ----
    stage1(0, wb[0]);
    CP_COMMIT();
    {
        const int r = tid >> 2, q = tid & 3;
        const int n = base + r;
        uint16_t* row = X1 + r * 216;
        if (n < N_NODES) {
            const int op = op_id[n], sv = sv_id[n], st = st_id[n];
            const uint4* so = (const uint4*)(g_pOpE + (size_t)op*EMB + q*16);
            const uint4* ss = (const uint4*)(g_pSvE + (size_t)sv*EMB + q*16);
            const uint4* st4 = (const uint4*)(g_pStE + (size_t)st*EMB + q*16);
            *(uint4*)(row + q*16)          = __ldg(so);
            *(uint4*)(row + q*16 + 8)      = __ldg(so + 1);
            *(uint4*)(row + 64 + q*16)     = __ldg(ss);
            *(uint4*)(row + 64 + q*16 + 8) = __ldg(ss + 1);
            *(uint4*)(row + 128 + q*16)    = __ldg(st4);
            *(uint4*)(row + 128 + q*16 + 8)= __ldg(st4 + 1);
            if (q == 0) {
                const float4 v0 = __ldg((const float4*)(lat + (size_t)n*LDIM));
                const float4 v1 = __ldg((const float4*)(lat + (size_t)n*LDIM + 4));
                *(uint4*)(row + 192) = make_uint4(bf2(v0.x,v0.y), bf2(v0.z,v0.w),
                                                  bf2(v1.x,v1.y), bf2(v1.z,v1.w));
            } else if (q == 1) {
                *(uint4*)(row + 200) = make_uint4(0u,0u,0u,0u);
            }
        } else {
            const uint4 z4 = make_uint4(0u,0u,0u,0u);
            *(uint4*)(row + q*16)           = z4;
            *(uint4*)(row + q*16 + 8)       = z4;
            *(uint4*)(row + 64 + q*16)      = z4;
            *(uint4*)(row + 64 + q*16 + 8)  = z4;
            *(uint4*)(row + 128 + q*16)     = z4;
            *(uint4*)(row + 128 + q*16 + 8) = z4;
            if (q == 0)      *(uint4*)(row + 192) = z4;
            else if (q == 1) *(uint4*)(row + 200) = z4;
        }
    }
    stage1(1, wb[1]);
    CP_COMMIT();
    CP_WAIT(1);
    __syncthreads();

    // ---- GEMM1: h = relu(X1 @ W1 + b1), K=208, double-buffered ----
    float acc1[2][4][4];
    #pragma unroll
    for (int i = 0; i < 2; i++)
        #pragma unroll
        for (int nt = 0; nt < 4; nt++)
            #pragma unroll
            for (int j = 0; j < 4; j++) acc1[i][nt][j] = 0.f;

    const int mp  = w & 1;
    const int nq1 = w >> 1;

    for (int ch = 0; ch < 4; ch++) {
        const uint32_t* Wc = (const uint32_t*)(smraw + ((ch & 1) ? 45056 : 27648));
        const int nsteps = (ch < 3) ? 4 : 1;
        for (int s = 0; s < nsteps; s++) {
            const int koff = s << 3;
            const int kidx = ch*64 + (s << 4);
            uint32_t a0[4], a1[4];
            const uint32_t addr = x1b + (mp*32 + (lane & 15)) * 432
                                + ((kidx + ((lane >> 4) << 3)) << 1);
            ldsm_x4(a0[0], a0[1], a0[2], a0[3], addr);
            ldsm_x4(a1[0], a1[1], a1[2], a1[3], addr + 16*432);
            #pragma unroll
            for (int nt = 0; nt < 4; nt++) {
                const int ncol = nq1*32 + nt*8 + g;
                const uint32_t b0 = Wc[(koff + t)*136 + ncol];
                const uint32_t bv = Wc[(koff + 4 + t)*136 + ncol];
                mma_bf16(acc1[0][nt], a0, b0, bv);
                mma_bf16(acc1[1][nt], a1, b0, bv);
            }
        }
        if (ch < 3) {
            __syncthreads();
            if (ch + 2 < 4) {
                stage1(ch + 2, wb[ch & 1]);
                CP_COMMIT();
                CP_WAIT(1);
            } else {
                CP_WAIT(0);
            }
            __syncthreads();
        }
    }
    __syncthreads();

    // ---- prefetch ALL of W2 (aliases X1 region) ----
    #pragma unroll
    for (int i = 0; i < 16; i++) {
        const int idx = tid + i*256;
        const int kp_l = idx >> 6, n4 = (idx & 63) << 2;
        cpa16(smem_u32(Wp2 + kp_l*264 + n4),
              g_pW2 + (size_t)kp_l*256 + n4);
    }
    CP_COMMIT();

    // ---- h = relu(+bias) -> Hs bf16 (overlaps W2 prefetch) ----
    #pragma unroll
    for (int i = 0; i < 2; i++)
        #pragma unroll
        for (int nt = 0; nt < 4; nt++) {
            const int r = mp*32 + i*16 + g;
            const int c = nq1*32 + nt*8 + 2*t;
            const float bA = __ldg(b1 + c), bB = __ldg(b1 + c + 1);
            ((uint32_t*)Hs)[r*68 + (c>>1)] =
                bf2(fmaxf(acc1[i][nt][0] + bA, 0.f), fmaxf(acc1[i][nt][1] + bB, 0.f));
            ((uint32_t*)Hs)[(r+8)*68 + (c>>1)] =
                bf2(fmaxf(acc1[i][nt][2] + bA, 0.f), fmaxf(acc1[i][nt][3] + bB, 0.f));
        }
    CP_WAIT(0);
    __syncthreads();

    // ---- GEMM2: y = h @ W2, K=128 (sync-free), paired mu/lv per warp ----
    float acc2[4][4][4];
    #pragma unroll
    for (int mi = 0; mi < 4; mi++)
        #pragma unroll
        for (int j = 0; j < 4; j++)
            #pragma unroll
            for (int e = 0; e < 4; e++) acc2[mi][j][e] = 0.f;

    for (int s = 0; s < 8; s++) {
        const int koff = s << 3;
        const int kidx = s << 4;
        uint32_t a[4][4];
        #pragma unroll
        for (int mi = 0; mi < 4; mi++) {
            const uint32_t addr = hsb + (mi*16 + (lane & 15)) * 272
                                + ((kidx + ((lane >> 4) << 3)) << 1);
            ldsm_x4(a[mi][0], a[mi][1], a[mi][2], a[mi][3], addr);
        }
        #pragma unroll
        for (int j = 0; j < 4; j++) {
            const int cb = (j < 2) ? (w*16 + 8*j) : (FDIM + w*16 + 8*(j-2));
            const uint32_t b0 = Wp2[(koff + t)*264 + cb + g];
            const uint32_t bv = Wp2[(koff + 4 + t)*264 + cb + g];
            #pragma unroll
            for (int mi = 0; mi < 4; mi++)
                mma_bf16(acc2[mi][j], a[mi], b0, bv);
        }
    }

    // ---- epilogue: z = mu + exp(0.5*tanh(lv))*eps -> g_zh, KL (approx math) ----
    float klw = 0.f;
    #pragma unroll
    for (int j = 0; j < 2; j++) {
        const int c = w*16 + 8*j + 2*t;
        const float bmx = __ldg(b2 + c),        bmy = __ldg(b2 + c + 1);
        const float blx = __ldg(b2 + FDIM + c), bly = __ldg(b2 + FDIM + c + 1);
        #pragma unroll
        for (int mi = 0; mi < 4; mi++) {
            const float* fm = acc2[mi][j];
            const float* fl = acc2[mi][j+2];
            #pragma unroll
            for (int half = 0; half < 2; half++) {
                const int r = mi*16 + g + half*8;
                const int n = base + r;
                if (n < N_NODES) {
                    const float mux = fm[2*half]   + bmx;
                    const float muy = fm[2*half+1] + bmy;
                    const float lvx = ftanh(fl[2*half]   + blx);
                    const float lvy = ftanh(fl[2*half+1] + bly);
                    const float2 e = __ldg((const float2*)(eps + (size_t)n*FDIM + c));
                    const float zx = mux + fexp(0.5f*lvx) * e.x;
                    const float zy = muy + fexp(0.5f*lvy) * e.y;
                    ((uint32_t*)g_zh)[(size_t)n*64 + (c>>1)] = bf2(zx, zy);
                    klw += lvx + 1.f - fexp(lvx) - mux*mux;
                    klw += lvy + 1.f - fexp(lvy) - muy*muy;
                }
            }
        }
    }
    #pragma unroll
    for (int o = 16; o; o >>= 1) klw += __shfl_xor_sync(0xffffffffu, klw, o);
    if (lane == 0) skl[w] = klw;
    __syncthreads();
    if (tid == 0) {
        double s = 0.0;
        #pragma unroll
        for (int i = 0; i < 8; i++) s += (double)skl[i];
        atomicAdd(&g_kl_sum, s);
    }
}

// ----------------------------------------------------------------------------
// Kernel 2: edge scatter-add — 8 edges/warp, 16B slices, MLP-4 unroll
// ----------------------------------------------------------------------------
__global__ void scatter_kernel(const int* __restrict__ esrc,
                               const int* __restrict__ edst)
{
    const int warp = (blockIdx.x * blockDim.x + threadIdx.x) >> 5;
    const int lane = threadIdx.x & 31;
    const int sub  = lane >> 4;
    const int off  = lane & 15;
    const int ebase = warp * 8 + sub;

    int   s[4], d[4];
    uint4 v[4];
    #pragma unroll
    for (int i = 0; i < 4; i++) {
        const int e = ebase + 2*i;
        s[i] = (e < N_EDGES) ? __ldg(esrc + e) : 0;
        d[i] = (e < N_EDGES) ? __ldg(edst + e) : 0;
    }
    #pragma unroll
    for (int i = 0; i < 4; i++)
        v[i] = __ldg((const uint4*)(g_zh + (size_t)s[i] * FDIM) + off);
    #pragma unroll
    for (int i = 0; i < 4; i++) {
        const int e = ebase + 2*i;
        if (e < N_EDGES) {
            uint32_t* p = (uint32_t*)(g_agg + (size_t)d[i] * FDIM) + 4*off;
            asm volatile("red.global.add.noftz.v4.bf16x2 [%0], {%1, %2, %3, %4};"
                         :: "l"(p), "r"(v[i].x), "r"(v[i].y), "r"(v[i].z), "r"(v[i].w)
                         : "memory");
        }
    }
}

// ----------------------------------------------------------------------------
// Kernel 3: decoder (bf16 mma, cp.async pipelined, 32-kpair chunks, occ 3)
// ----------------------------------------------------------------------------
extern "C" __global__ void __launch_bounds__(256, 3)
dec_kernel(const int*   __restrict__ op_id,
           const float* __restrict__ lat,
           const float* __restrict__ mub,
           const float* __restrict__ lvb,
           const float* __restrict__ opw,
           float* __restrict__ op_loss,
           float* __restrict__ op_cnt)
{
    extern __shared__ __align__(16) char smraw[];
    uint16_t* X   = (uint16_t*)smraw;               // [64][264]
    uint16_t* Yd  = (uint16_t*)smraw;               // [64][136] (post-GEMM)
    uint32_t* Whp = (uint32_t*)(smraw + 17408);     // [64][24]
    float*    Yh  = (float*)(smraw + 23552);        // [64][20]
    __shared__ float sL[8];

    const int tid  = threadIdx.x;
    const int lane = tid & 31;
    const int w    = tid >> 5;
    const int base = blockIdx.x * TILE;
    const int g    = lane >> 2;
    const int t    = lane & 3;
    const uint32_t xb  = smem_u32(X);
    const uint32_t ydb = smem_u32(Yd);
    const uint32_t wbuf[2] = { smem_u32(smraw + 33792), smem_u32(smraw + 51200) };

    auto staged = [&](int ch, uint32_t wdst) {
        #pragma unroll
        for (int i = 0; i < 4; i++) {
            const int idx = tid + i*256;
            const int kp_l = idx >> 5, n4 = (idx & 31) << 2;
            cpa16(wdst + (kp_l*136 + n4)*4,
                  g_pWd + (size_t)(ch*32 + kp_l)*FDIM + n4);
        }
    };

    // ---- prologue: chunk0 || X gather || chunk1 ----
    staged(0, wbuf[0]);
    CP_COMMIT();
    #pragma unroll
    for (int it = 0; it < 8; it++) {
        const int u = tid + it*256;
        const int r = u >> 5, half = (u >> 4) & 1, seg = u & 15;
        const int n = base + r;
        const uint32_t dst = xb + (r*264 + half*128 + seg*8) * 2;
        if (n < N_NODES) {
            const uint16_t* src = (half ? g_agg : g_zh) + (size_t)n*FDIM + seg*8;
            cpa16(dst, src);
        } else {
            *(uint4*)((char*)X + (dst - xb)) = make_uint4(0u,0u,0u,0u);
        }
    }
    CP_COMMIT();
    staged(1, wbuf[1]);
    CP_COMMIT();
    CP_WAIT(1);
    __syncthreads();

    // ---- GEMM: yd = relu([z|agg] @ [Wself;Wagg]), K=256, double-buffered ----
    float acc[2][4][4];
    #pragma unroll
    for (int i = 0; i < 2; i++)
        #pragma unroll
        for (int nt = 0; nt < 4; nt++)
            #pragma unroll
            for (int e = 0; e < 4; e++) acc[i][nt][e] = 0.f;

    const int mp  = w & 1;
    const int nqd = w >> 1;

    for (int ch = 0; ch < 4; ch++) {
        const uint32_t* Wc = (const uint32_t*)(smraw + ((ch & 1) ? 51200 : 33792));
        for (int s = 0; s < 4; s++) {
            const int koff = s << 3;
            const int kidx = ch*64 + (s << 4);
            uint32_t a0[4], a1[4];
            const uint32_t addr = xb + (mp*32 + (lane & 15)) * 528
                                + ((kidx + ((lane >> 4) << 3)) << 1);
            ldsm_x4(a0[0], a0[1], a0[2], a0[3], addr);
            ldsm_x4(a1[0], a1[1], a1[2], a1[3], addr + 16*528);
            #pragma unroll
            for (int nt = 0; nt < 4; nt++) {
                const int ncol = nqd*32 + nt*8 + g;
                const uint32_t b0 = Wc[(koff + t)*136 + ncol];
                const uint32_t bv = Wc[(koff + 4 + t)*136 + ncol];
                mma_bf16(acc[0][nt], a0, b0, bv);
                mma_bf16(acc[1][nt], a1, b0, bv);
            }
        }
        if (ch < 3) {
            __syncthreads();
            if (ch + 2 < 4) {
                staged(ch + 2, wbuf[ch & 1]);
                CP_COMMIT();
                CP_WAIT(1);
            } else {
                CP_WAIT(0);
            }
            __syncthreads();
        }
    }
    __syncthreads();

    // ---- yd = relu -> Yd bf16 ; stage heads weights ----
    #pragma unroll
    for (int i = 0; i < 2; i++)
        #pragma unroll
        for (int nt = 0; nt < 4; nt++) {
            const int r = mp*32 + i*16 + g;
            const int c = nqd*32 + nt*8 + 2*t;
            ((uint32_t*)Yd)[r*68 + (c>>1)] =
                bf2(fmaxf(acc[i][nt][0], 0.f), fmaxf(acc[i][nt][1], 0.f));
            ((uint32_t*)Yd)[(r+8)*68 + (c>>1)] =
                bf2(fmaxf(acc[i][nt][2], 0.f), fmaxf(acc[i][nt][3], 0.f));
        }
    #pragma unroll
    for (int i = 0; i < 4; i++) {
        const int idx = tid + i*256;
        const int kp = idx >> 4, nn = idx & 15;
        Whp[kp*24 + nn] = g_pWh[kp*16 + nn];
    }
    __syncthreads();

    // ---- heads mma: Yh[64][16] = yd @ [muW|lvW] + bias ----
    {
        const int mt = w & 3;
        const int nh = (w >> 2) & 1;
        float ah[4] = {0.f, 0.f, 0.f, 0.f};
        for (int s = 0; s < 8; s++) {
            const int koff = s << 3;
            uint32_t a[4];
            const uint32_t addr = ydb + (mt*16 + (lane & 15)) * 272
                                + (((s << 4) + ((lane >> 4) << 3)) << 1);
            ldsm_x4(a[0], a[1], a[2], a[3], addr);
            const uint32_t b0 = Whp[(koff + t)*24 + nh*8 + g];
            const uint32_t bv = Whp[(koff + 4 + t)*24 + nh*8 + g];
            mma_bf16(ah, a, b0, bv);
        }
        const int r = mt*16 + g;
        const int c = nh*8 + 2*t;
        const float* bp = nh ? lvb : mub;
        const float bx = __ldg(bp + 2*t), by = __ldg(bp + 2*t + 1);
        Yh[r*20 + c]         = ah[0] + bx;
        Yh[r*20 + c + 1]     = ah[1] + by;
        Yh[(r+8)*20 + c]     = ah[2] + bx;
        Yh[(r+8)*20 + c + 1] = ah[3] + by;
    }
    __syncthreads();

    // ---- loss: thread = (node r = tid>>2, k-pair kg = tid&3) ----
    {
        const int r  = tid >> 2;
        const int kg = tid & 3;
        const int n  = base + r;
        const bool valid = (n < N_NODES);
        float part = 0.f;
        int op = 0;
        if (valid) {
            op = __ldg(op_id + n);
            const float4 muA = *(const float4*)(Yh + r*20);
            const float4 muB = *(const float4*)(Yh + r*20 + 4);
            const float4 lvA = *(const float4*)(Yh + r*20 + 8);
            const float4 lvB = *(const float4*)(Yh + r*20 + 12);
            const float muv[8] = { muA.x, muA.y, muA.z, muA.w, muB.x, muB.y, muB.z, muB.w };
            const float lvv[8] = { lvA.x, lvA.y, lvA.z, lvA.w, lvB.x, lvB.y, lvB.z, lvB.w };
            const float* wrow = opw + (size_t)op * (2 * LDIM * LDIM);
            float mpA = 0.f, mpB = 0.f, lpA = 0.f, lpB = 0.f;
            #pragma unroll
            for (int l = 0; l < LDIM; l++) {
                const float2 wm = __ldg((const float2*)(wrow + l*2*LDIM + 2*kg));
                const float2 wl = __ldg((const float2*)(wrow + l*2*LDIM + LDIM + 2*kg));
                mpA += muv[l] * wm.x; mpB += muv[l] * wm.y;
                lpA += lvv[l] * wl.x; lpB += lvv[l] * wl.y;
            }
            const float2 lab = __ldg((const float2*)(lat + (size_t)n*LDIM + 2*kg));
            const float dA = mpA - lab.x, dB = mpB - lab.y;
            part = dA*dA / (2.f*fexp(lpA) + 1e-7f) + 0.5f*lpA
                 + dB*dB / (2.f*fexp(lpB) + 1e-7f) + 0.5f*lpB;
        }
        part += __shfl_xor_sync(0xffffffffu, part, 1);
        part += __shfl_xor_sync(0xffffffffu, part, 2);
        const float lossn = part * (1.f / LDIM);
        if (valid && kg == 0) {
            atomicAdd(op_loss + op, lossn);
            atomicAdd(op_cnt  + op, 1.f);
        }
        float wval = (valid && kg == 0) ? lossn : 0.f;
        wval += __shfl_xor_sync(0xffffffffu, wval, 4);
        wval += __shfl_xor_sync(0xffffffffu, wval, 8);
        wval += __shfl_xor_sync(0xffffffffu, wval, 16);
        if (lane == 0) sL[w] = wval;
    }
    __syncthreads();
    if (tid == 0) {
        double s = 0.0;
        #pragma unroll
        for (int i = 0; i < 8; i++) s += (double)sL[i];
        atomicAdd(&g_lat_sum, s);
    }
}

// ----------------------------------------------------------------------------
// Kernel 4: finalize
// ----------------------------------------------------------------------------
__global__ void fin_kernel(float* __restrict__ out)
{
    if (threadIdx.x == 0) {
        const double lat_loss = g_lat_sum / (double)N_NODES;
        const double kl = -0.5 * (g_kl_sum / ((double)N_NODES * (double)FDIM));
        out[0] = (float)(lat_loss + kl);
    }
}

// ----------------------------------------------------------------------------
extern "C" void kernel_launch(void* const* d_in, const int* in_sizes, int n_in,
                              void* d_out, int out_size)
{
    const int*   op_id = (const int*)  d_in[0];
    const int*   sv_id = (const int*)  d_in[1];
    const int*   st_id = (const int*)  d_in[2];
    const float* lat   = (const float*)d_in[3];
    const int*   esrc  = (const int*)  d_in[4];
    const int*   edst  = (const int*)  d_in[5];
    const float* eps   = (const float*)d_in[6];
    const float* opE   = (const float*)d_in[7];
    const float* svE   = (const float*)d_in[8];
    const float* stE   = (const float*)d_in[9];
    const float* W1    = (const float*)d_in[10];
    const float* b1    = (const float*)d_in[11];
    const float* W2    = (const float*)d_in[12];
    const float* b2    = (const float*)d_in[13];
    const float* Wself = (const float*)d_in[14];
    const float* Wagg  = (const float*)d_in[15];
    const float* muW   = (const float*)d_in[16];
    const float* mub   = (const float*)d_in[17];
    const float* lvW   = (const float*)d_in[18];
    const float* lvb   = (const float*)d_in[19];
    const float* opw   = (const float*)d_in[20];

    float* out     = (float*)d_out;
    float* op_loss = out + 1;
    float* op_cnt  = out + 1 + OPC;

    const int ENC_SMEM = 84992;
    const int DEC_SMEM = 68608;
    static bool attr_done = false;
    if (!attr_done) {
        cudaFuncSetAttribute(enc_kernel, cudaFuncAttributeMaxDynamicSharedMemorySize, ENC_SMEM);
        cudaFuncSetAttribute(dec_kernel, cudaFuncAttributeMaxDynamicSharedMemorySize, DEC_SMEM);
        attr_done = true;
    }

    const int n_tiles = (N_NODES + TILE - 1) / TILE;   // 7813

    zero_prep_kernel<<<31250, 256>>>(out, W1, W2, Wself, Wagg, muW, lvW,
                                     opE, svE, stE);

    enc_kernel<<<n_tiles, 256, ENC_SMEM>>>(op_id, sv_id, st_id, lat, eps, b1, b2);

    scatter_kernel<<<15625, 256>>>(esrc, edst);

    dec_kernel<<<n_tiles, 256, DEC_SMEM>>>(op_id, lat, mub, lvb, opw,
                                           op_loss, op_cnt);

    fin_kernel<<<1, 32>>>(out);
}

// round 16
// speedup vs baseline: 1.0813x; 1.0066x over previous
#include <cuda_runtime.h>
#include <cstdint>

#define N_NODES 500000
#define N_EDGES 1000000
#define EMB 64
#define FDIM 128
#define LDIM 8
#define OPC 5000

#define TILE 64

// ---- scratch (no allocations allowed) ----
__device__ uint16_t g_zh [(size_t)N_NODES * FDIM];   // z in bf16 (128 MB)
__device__ uint16_t g_agg[(size_t)N_NODES * FDIM];   // agg in bf16 (128 MB)
__device__ double   g_kl_sum;
__device__ double   g_lat_sum;

// ---- pre-packed weights/embeddings (bf16) ----
__device__ uint32_t g_pW1[128 * 128];
__device__ uint32_t g_pW2[64 * 256];
__device__ uint32_t g_pWd[128 * 128];
__device__ uint32_t g_pWh[64 * 16];
__device__ uint16_t g_pOpE[OPC * EMB];
__device__ uint16_t g_pSvE[2000 * EMB];
__device__ uint16_t g_pStE[16 * EMB];

// ---- helpers ----
__device__ __forceinline__ uint32_t smem_u32(const void* p) {
    uint32_t a;
    asm("{ .reg .u64 t; cvta.to.shared.u64 t, %1; cvt.u32.u64 %0, t; }"
        : "=r"(a) : "l"(p));
    return a;
}
__device__ __forceinline__ void ldsm_x4(uint32_t& r0, uint32_t& r1,
                                        uint32_t& r2, uint32_t& r3,
                                        uint32_t addr) {
    asm volatile("ldmatrix.sync.aligned.m8n8.x4.shared.b16 {%0,%1,%2,%3}, [%4];"
                 : "=r"(r0), "=r"(r1), "=r"(r2), "=r"(r3) : "r"(addr));
}
__device__ __forceinline__ void mma_bf16(float* d, const uint32_t* a,
                                         uint32_t b0, uint32_t b1) {
    asm volatile("mma.sync.aligned.m16n8k16.row.col.f32.bf16.bf16.f32 "
                 "{%0,%1,%2,%3}, {%4,%5,%6,%7}, {%8,%9}, {%0,%1,%2,%3};"
                 : "+f"(d[0]), "+f"(d[1]), "+f"(d[2]), "+f"(d[3])
                 : "r"(a[0]), "r"(a[1]), "r"(a[2]), "r"(a[3]),
                   "r"(b0), "r"(b1));
}
__device__ __forceinline__ uint32_t bf2(float lo, float hi) {
    uint32_t d;
    asm("cvt.rn.satfinite.bf16x2.f32 %0, %1, %2;" : "=r"(d) : "f"(hi), "f"(lo));
    return d;
}
__device__ __forceinline__ void cpa16(uint32_t dst, const void* src) {
    asm volatile("cp.async.cg.shared.global [%0], [%1], 16;"
                 :: "r"(dst), "l"(src) : "memory");
}
#define CP_COMMIT() asm volatile("cp.async.commit_group;" ::: "memory")
#define CP_WAIT(n)  asm volatile("cp.async.wait_group %0;" :: "n"(n) : "memory")

// fast transcendentals (HW approx; |err| far below the 1e-3 gate)
__device__ __forceinline__ float fexp(float x) {
    float r;
    asm("ex2.approx.f32 %0, %1;" : "=f"(r) : "f"(x * 1.4426950408889634f));
    return r;
}
__device__ __forceinline__ float ftanh(float x) {
    float r;
    asm("tanh.approx.f32 %0, %1;" : "=f"(r) : "f"(x));
    return r;
}

// ----------------------------------------------------------------------------
// Kernel 0: pack weights/embeddings + zero out head + scalars.
//           (agg zeroing moved into enc_kernel — each block zeroes its nodes.)
// ----------------------------------------------------------------------------
__global__ void prep_kernel(float* __restrict__ out,
                            const float* __restrict__ W1,
                            const float* __restrict__ W2,
                            const float* __restrict__ Wself,
                            const float* __restrict__ Wagg,
                            const float* __restrict__ muW,
                            const float* __restrict__ lvW,
                            const float* __restrict__ opE,
                            const float* __restrict__ svE,
                            const float* __restrict__ stE)
{
    const int i = blockIdx.x * blockDim.x + threadIdx.x;
    if (i < 1 + 2*OPC) out[i] = 0.f;
    if (i == 0) { g_kl_sum = 0.0; g_lat_sum = 0.0; }

    if (i < 16384) {
        const int kp = i >> 7, n = i & 127;
        const int k0 = 2 * kp;
        const float lo = (k0 < 200)     ? __ldg(W1 + (size_t)k0 * FDIM + n)     : 0.f;
        const float hi = (k0 + 1 < 200) ? __ldg(W1 + (size_t)(k0+1) * FDIM + n) : 0.f;
        g_pW1[i] = bf2(lo, hi);
    } else if (i < 32768) {
        const int j = i - 16384;
        const int kp = j >> 8, n = j & 255;
        const int k0 = 2 * kp;
        g_pW2[j] = bf2(__ldg(W2 + (size_t)k0 * 256 + n),
                       __ldg(W2 + (size_t)(k0+1) * 256 + n));
    } else if (i < 49152) {
        const int j = i - 32768;
        const int kp = j >> 7, n = j & 127;
        const float* src = (kp < 64) ? Wself : Wagg;
        const int k0 = (kp < 64) ? 2*kp : 2*(kp - 64);
        g_pWd[j] = bf2(__ldg(src + (size_t)k0 * FDIM + n),
                       __ldg(src + (size_t)(k0+1) * FDIM + n));
    } else if (i < 50176) {
        const int j = i - 49152;
        const int kp = j >> 4, nn = j & 15;
        float lo, hi;
        if (nn < 8) {
            lo = __ldg(muW + (size_t)(2*kp) * LDIM + nn);
            hi = __ldg(muW + (size_t)(2*kp+1) * LDIM + nn);
        } else {
            lo = __ldg(lvW + (size_t)(2*kp) * LDIM + nn - 8);
            hi = __ldg(lvW + (size_t)(2*kp+1) * LDIM + nn - 8);
        }
        g_pWh[j] = bf2(lo, hi);
    } else if (i < 210176) {
        const int j = i - 50176;
        const float2 v = __ldg((const float2*)(opE + 2*(size_t)j));
        ((uint32_t*)g_pOpE)[j] = bf2(v.x, v.y);
    } else if (i < 274176) {
        const int j = i - 210176;
        const float2 v = __ldg((const float2*)(svE + 2*(size_t)j));
        ((uint32_t*)g_pSvE)[j] = bf2(v.x, v.y);
    } else if (i < 274688) {
        const int j = i - 274176;
        const float2 v = __ldg((const float2*)(stE + 2*(size_t)j));
        ((uint32_t*)g_pStE)[j] = bf2(v.x, v.y);
    }
}

// ----------------------------------------------------------------------------
// Kernel 1: encoder (bf16 mma), 64-node tile, 256 threads, cp.async pipeline.
//           Also zeroes this tile's g_agg rows (overlapped fire-and-forget STGs).
// ----------------------------------------------------------------------------
extern "C" __global__ void __launch_bounds__(256, 2)
enc_kernel(const int*   __restrict__ op_id,
           const int*   __restrict__ sv_id,
           const int*   __restrict__ st_id,
           const float* __restrict__ lat,
           const float* __restrict__ eps,
           const float* __restrict__ b1,
           const float* __restrict__ b2)
{
    extern __shared__ __align__(16) char smraw[];
    uint16_t* X1  = (uint16_t*)smraw;               // [64][216]
    uint16_t* Hs  = (uint16_t*)(smraw + 67584);     // [64][136]
    uint32_t* Wp2 = (uint32_t*)smraw;               // [64][264]
    __shared__ float skl[8];

    const int tid  = threadIdx.x;
    const int lane = tid & 31;
    const int w    = tid >> 5;
    const int base = blockIdx.x * TILE;
    const int g    = lane >> 2;
    const int t    = lane & 3;
    const uint32_t x1b  = smem_u32(X1);
    const uint32_t hsb  = smem_u32(Hs);
    const uint32_t wb[2] = { smem_u32(smraw + 27648), smem_u32(smraw + 45056) };

    auto stage1 = [&](int ch, uint32_t wbuf) {
        #pragma unroll
        for (int i = 0; i < 4; i++) {
            const int idx = tid + i*256;
            const int kp_l = idx >> 5, n4 = (idx & 31) << 2;
            cpa16(wbuf + (kp_l*136 + n4)*4,
                  g_pW1 + (size_t)(ch*32 + kp_l)*FDIM + n4);
        }
    };

    // ---- prologue ----
    stage1(0, wb[0]);
    CP_COMMIT();

    // zero this tile's agg rows: 64 rows x 16 uint4 = 1024 units, 4/thread
    {
        const uint4 z4 = make_uint4(0u, 0u, 0u, 0u);
        #pragma unroll
        for (int i = 0; i < 4; i++) {
            const int idx = tid + i*256;
            const int r = idx >> 4, u = idx & 15;
            const int n = base + r;
            if (n < N_NODES)
                ((uint4*)(g_agg + (size_t)n * FDIM))[u] = z4;
        }
    }

    {
        const int r = tid >> 2, q = tid & 3;
        const int n = base + r;
        uint16_t* row = X1 + r * 216;
        if (n < N_NODES) {
            const int op = op_id[n], sv = sv_id[n], st = st_id[n];
            const uint4* so = (const uint4*)(g_pOpE + (size_t)op*EMB + q*16);
            const uint4* ss = (const uint4*)(g_pSvE + (size_t)sv*EMB + q*16);
            const uint4* st4 = (const uint4*)(g_pStE + (size_t)st*EMB + q*16);
            *(uint4*)(row + q*16)          = __ldg(so);
            *(uint4*)(row + q*16 + 8)      = __ldg(so + 1);
            *(uint4*)(row + 64 + q*16)     = __ldg(ss);
            *(uint4*)(row + 64 + q*16 + 8) = __ldg(ss + 1);
            *(uint4*)(row + 128 + q*16)    = __ldg(st4);
            *(uint4*)(row + 128 + q*16 + 8)= __ldg(st4 + 1);
            if (q == 0) {
                const float4 v0 = __ldg((const float4*)(lat + (size_t)n*LDIM));
                const float4 v1 = __ldg((const float4*)(lat + (size_t)n*LDIM + 4));
                *(uint4*)(row + 192) = make_uint4(bf2(v0.x,v0.y), bf2(v0.z,v0.w),
                                                  bf2(v1.x,v1.y), bf2(v1.z,v1.w));
            } else if (q == 1) {
                *(uint4*)(row + 200) = make_uint4(0u,0u,0u,0u);
            }
        } else {
            const uint4 z4 = make_uint4(0u,0u,0u,0u);
            *(uint4*)(row + q*16)           = z4;
            *(uint4*)(row + q*16 + 8)       = z4;
            *(uint4*)(row + 64 + q*16)      = z4;
            *(uint4*)(row + 64 + q*16 + 8)  = z4;
            *(uint4*)(row + 128 + q*16)     = z4;
            *(uint4*)(row + 128 + q*16 + 8) = z4;
            if (q == 0)      *(uint4*)(row + 192) = z4;
            else if (q == 1) *(uint4*)(row + 200) = z4;
        }
    }
    stage1(1, wb[1]);
    CP_COMMIT();
    CP_WAIT(1);
    __syncthreads();

    // ---- GEMM1: h = relu(X1 @ W1 + b1), K=208, double-buffered ----
    float acc1[2][4][4];
    #pragma unroll
    for (int i = 0; i < 2; i++)
        #pragma unroll
        for (int nt = 0; nt < 4; nt++)
            #pragma unroll
            for (int j = 0; j < 4; j++) acc1[i][nt][j] = 0.f;

    const int mp  = w & 1;
    const int nq1 = w >> 1;

    for (int ch = 0; ch < 4; ch++) {
        const uint32_t* Wc = (const uint32_t*)(smraw + ((ch & 1) ? 45056 : 27648));
        const int nsteps = (ch < 3) ? 4 : 1;
        for (int s = 0; s < nsteps; s++) {
            const int koff = s << 3;
            const int kidx = ch*64 + (s << 4);
            uint32_t a0[4], a1[4];
            const uint32_t addr = x1b + (mp*32 + (lane & 15)) * 432
                                + ((kidx + ((lane >> 4) << 3)) << 1);
            ldsm_x4(a0[0], a0[1], a0[2], a0[3], addr);
            ldsm_x4(a1[0], a1[1], a1[2], a1[3], addr + 16*432);
            #pragma unroll
            for (int nt = 0; nt < 4; nt++) {
                const int ncol = nq1*32 + nt*8 + g;
                const uint32_t b0 = Wc[(koff + t)*136 + ncol];
                const uint32_t bv = Wc[(koff + 4 + t)*136 + ncol];
                mma_bf16(acc1[0][nt], a0, b0, bv);
                mma_bf16(acc1[1][nt], a1, b0, bv);
            }
        }
        if (ch < 3) {
            __syncthreads();
            if (ch + 2 < 4) {
                stage1(ch + 2, wb[ch & 1]);
                CP_COMMIT();
                CP_WAIT(1);
            } else {
                CP_WAIT(0);
            }
            __syncthreads();
        }
    }
    __syncthreads();

    // ---- prefetch ALL of W2 (aliases X1 region) ----
    #pragma unroll
    for (int i = 0; i < 16; i++) {
        const int idx = tid + i*256;
        const int kp_l = idx >> 6, n4 = (idx & 63) << 2;
        cpa16(smem_u32(Wp2 + kp_l*264 + n4),
              g_pW2 + (size_t)kp_l*256 + n4);
    }
    CP_COMMIT();

    // ---- h = relu(+bias) -> Hs bf16 (overlaps W2 prefetch) ----
    #pragma unroll
    for (int i = 0; i < 2; i++)
        #pragma unroll
        for (int nt = 0; nt < 4; nt++) {
            const int r = mp*32 + i*16 + g;
            const int c = nq1*32 + nt*8 + 2*t;
            const float bA = __ldg(b1 + c), bB = __ldg(b1 + c + 1);
            ((uint32_t*)Hs)[r*68 + (c>>1)] =
                bf2(fmaxf(acc1[i][nt][0] + bA, 0.f), fmaxf(acc1[i][nt][1] + bB, 0.f));
            ((uint32_t*)Hs)[(r+8)*68 + (c>>1)] =
                bf2(fmaxf(acc1[i][nt][2] + bA, 0.f), fmaxf(acc1[i][nt][3] + bB, 0.f));
        }
    CP_WAIT(0);
    __syncthreads();

    // ---- GEMM2: y = h @ W2, K=128 (sync-free), paired mu/lv per warp ----
    float acc2[4][4][4];
    #pragma unroll
    for (int mi = 0; mi < 4; mi++)
        #pragma unroll
        for (int j = 0; j < 4; j++)
            #pragma unroll
            for (int e = 0; e < 4; e++) acc2[mi][j][e] = 0.f;

    for (int s = 0; s < 8; s++) {
        const int koff = s << 3;
        const int kidx = s << 4;
        uint32_t a[4][4];
        #pragma unroll
        for (int mi = 0; mi < 4; mi++) {
            const uint32_t addr = hsb + (mi*16 + (lane & 15)) * 272
                                + ((kidx + ((lane >> 4) << 3)) << 1);
            ldsm_x4(a[mi][0], a[mi][1], a[mi][2], a[mi][3], addr);
        }
        #pragma unroll
        for (int j = 0; j < 4; j++) {
            const int cb = (j < 2) ? (w*16 + 8*j) : (FDIM + w*16 + 8*(j-2));
            const uint32_t b0 = Wp2[(koff + t)*264 + cb + g];
            const uint32_t bv = Wp2[(koff + 4 + t)*264 + cb + g];
            #pragma unroll
            for (int mi = 0; mi < 4; mi++)
                mma_bf16(acc2[mi][j], a[mi], b0, bv);
        }
    }

    // ---- epilogue: z = mu + exp(0.5*tanh(lv))*eps -> g_zh, KL (approx math) ----
    float klw = 0.f;
    #pragma unroll
    for (int j = 0; j < 2; j++) {
        const int c = w*16 + 8*j + 2*t;
        const float bmx = __ldg(b2 + c),        bmy = __ldg(b2 + c + 1);
        const float blx = __ldg(b2 + FDIM + c), bly = __ldg(b2 + FDIM + c + 1);
        #pragma unroll
        for (int mi = 0; mi < 4; mi++) {
            const float* fm = acc2[mi][j];
            const float* fl = acc2[mi][j+2];
            #pragma unroll
            for (int half = 0; half < 2; half++) {
                const int r = mi*16 + g + half*8;
                const int n = base + r;
                if (n < N_NODES) {
                    const float mux = fm[2*half]   + bmx;
                    const float muy = fm[2*half+1] + bmy;
                    const float lvx = ftanh(fl[2*half]   + blx);
                    const float lvy = ftanh(fl[2*half+1] + bly);
                    const float2 e = __ldg((const float2*)(eps + (size_t)n*FDIM + c));
                    const float zx = mux + fexp(0.5f*lvx) * e.x;
                    const float zy = muy + fexp(0.5f*lvy) * e.y;
                    ((uint32_t*)g_zh)[(size_t)n*64 + (c>>1)] = bf2(zx, zy);
                    klw += lvx + 1.f - fexp(lvx) - mux*mux;
                    klw += lvy + 1.f - fexp(lvy) - muy*muy;
                }
            }
        }
    }
    #pragma unroll
    for (int o = 16; o; o >>= 1) klw += __shfl_xor_sync(0xffffffffu, klw, o);
    if (lane == 0) skl[w] = klw;
    __syncthreads();
    if (tid == 0) {
        double s = 0.0;
        #pragma unroll
        for (int i = 0; i < 8; i++) s += (double)skl[i];
        atomicAdd(&g_kl_sum, s);
    }
}

// ----------------------------------------------------------------------------
// Kernel 2: edge scatter-add — 8 edges/warp, 16B slices, MLP-4 unroll
// ----------------------------------------------------------------------------
__global__ void scatter_kernel(const int* __restrict__ esrc,
                               const int* __restrict__ edst)
{
    const int warp = (blockIdx.x * blockDim.x + threadIdx.x) >> 5;
    const int lane = threadIdx.x & 31;
    const int sub  = lane >> 4;
    const int off  = lane & 15;
    const int ebase = warp * 8 + sub;

    int   s[4], d[4];
    uint4 v[4];
    #pragma unroll
    for (int i = 0; i < 4; i++) {
        const int e = ebase + 2*i;
        s[i] = (e < N_EDGES) ? __ldg(esrc + e) : 0;
        d[i] = (e < N_EDGES) ? __ldg(edst + e) : 0;
    }
    #pragma unroll
    for (int i = 0; i < 4; i++)
        v[i] = __ldg((const uint4*)(g_zh + (size_t)s[i] * FDIM) + off);
    #pragma unroll
    for (int i = 0; i < 4; i++) {
        const int e = ebase + 2*i;
        if (e < N_EDGES) {
            uint32_t* p = (uint32_t*)(g_agg + (size_t)d[i] * FDIM) + 4*off;
            asm volatile("red.global.add.noftz.v4.bf16x2 [%0], {%1, %2, %3, %4};"
                         :: "l"(p), "r"(v[i].x), "r"(v[i].y), "r"(v[i].z), "r"(v[i].w)
                         : "memory");
        }
    }
}

// ----------------------------------------------------------------------------
// Kernel 3: decoder (bf16 mma, cp.async pipelined, 32-kpair chunks, occ 3)
// ----------------------------------------------------------------------------
extern "C" __global__ void __launch_bounds__(256, 3)
dec_kernel(const int*   __restrict__ op_id,
           const float* __restrict__ lat,
           const float* __restrict__ mub,
           const float* __restrict__ lvb,
           const float* __restrict__ opw,
           float* __restrict__ op_loss,
           float* __restrict__ op_cnt)
{
    extern __shared__ __align__(16) char smraw[];
    uint16_t* X   = (uint16_t*)smraw;               // [64][264]
    uint16_t* Yd  = (uint16_t*)smraw;               // [64][136] (post-GEMM)
    uint32_t* Whp = (uint32_t*)(smraw + 17408);     // [64][24]
    float*    Yh  = (float*)(smraw + 23552);        // [64][20]
    __shared__ float sL[8];

    const int tid  = threadIdx.x;
    const int lane = tid & 31;
    const int w    = tid >> 5;
    const int base = blockIdx.x * TILE;
    const int g    = lane >> 2;
    const int t    = lane & 3;
    const uint32_t xb  = smem_u32(X);
    const uint32_t ydb = smem_u32(Yd);
    const uint32_t wbuf[2] = { smem_u32(smraw + 33792), smem_u32(smraw + 51200) };

    auto staged = [&](int ch, uint32_t wdst) {
        #pragma unroll
        for (int i = 0; i < 4; i++) {
            const int idx = tid + i*256;
            const int kp_l = idx >> 5, n4 = (idx & 31) << 2;
            cpa16(wdst + (kp_l*136 + n4)*4,
                  g_pWd + (size_t)(ch*32 + kp_l)*FDIM + n4);
        }
    };

    // ---- prologue: chunk0 || X gather || chunk1 ----
    staged(0, wbuf[0]);
    CP_COMMIT();
    #pragma unroll
    for (int it = 0; it < 8; it++) {
        const int u = tid + it*256;
        const int r = u >> 5, half = (u >> 4) & 1, seg = u & 15;
        const int n = base + r;
        const uint32_t dst = xb + (r*264 + half*128 + seg*8) * 2;
        if (n < N_NODES) {
            const uint16_t* src = (half ? g_agg : g_zh) + (size_t)n*FDIM + seg*8;
            cpa16(dst, src);
        } else {
            *(uint4*)((char*)X + (dst - xb)) = make_uint4(0u,0u,0u,0u);
        }
    }
    CP_COMMIT();
    staged(1, wbuf[1]);
    CP_COMMIT();
    CP_WAIT(1);
    __syncthreads();

    // ---- GEMM: yd = relu([z|agg] @ [Wself;Wagg]), K=256, double-buffered ----
    float acc[2][4][4];
    #pragma unroll
    for (int i = 0; i < 2; i++)
        #pragma unroll
        for (int nt = 0; nt < 4; nt++)
            #pragma unroll
            for (int e = 0; e < 4; e++) acc[i][nt][e] = 0.f;

    const int mp  = w & 1;
    const int nqd = w >> 1;

    for (int ch = 0; ch < 4; ch++) {
        const uint32_t* Wc = (const uint32_t*)(smraw + ((ch & 1) ? 51200 : 33792));
        for (int s = 0; s < 4; s++) {
            const int koff = s << 3;
            const int kidx = ch*64 + (s << 4);
            uint32_t a0[4], a1[4];
            const uint32_t addr = xb + (mp*32 + (lane & 15)) * 528
                                + ((kidx + ((lane >> 4) << 3)) << 1);
            ldsm_x4(a0[0], a0[1], a0[2], a0[3], addr);
            ldsm_x4(a1[0], a1[1], a1[2], a1[3], addr + 16*528);
            #pragma unroll
            for (int nt = 0; nt < 4; nt++) {
                const int ncol = nqd*32 + nt*8 + g;
                const uint32_t b0 = Wc[(koff + t)*136 + ncol];
                const uint32_t bv = Wc[(koff + 4 + t)*136 + ncol];
                mma_bf16(acc[0][nt], a0, b0, bv);
                mma_bf16(acc[1][nt], a1, b0, bv);
            }
        }
        if (ch < 3) {
            __syncthreads();
            if (ch + 2 < 4) {
                staged(ch + 2, wbuf[ch & 1]);
                CP_COMMIT();
                CP_WAIT(1);
            } else {
                CP_WAIT(0);
            }
            __syncthreads();
        }
    }
    __syncthreads();

    // ---- yd = relu -> Yd bf16 ; stage heads weights ----
    #pragma unroll
    for (int i = 0; i < 2; i++)
        #pragma unroll
        for (int nt = 0; nt < 4; nt++) {
            const int r = mp*32 + i*16 + g;
            const int c = nqd*32 + nt*8 + 2*t;
            ((uint32_t*)Yd)[r*68 + (c>>1)] =
                bf2(fmaxf(acc[i][nt][0], 0.f), fmaxf(acc[i][nt][1], 0.f));
            ((uint32_t*)Yd)[(r+8)*68 + (c>>1)] =
                bf2(fmaxf(acc[i][nt][2], 0.f), fmaxf(acc[i][nt][3], 0.f));
        }
    #pragma unroll
    for (int i = 0; i < 4; i++) {
        const int idx = tid + i*256;
        const int kp = idx >> 4, nn = idx & 15;
        Whp[kp*24 + nn] = g_pWh[kp*16 + nn];
    }
    __syncthreads();

    // ---- heads mma: Yh[64][16] = yd @ [muW|lvW] + bias ----
    {
        const int mt = w & 3;
        const int nh = (w >> 2) & 1;
        float ah[4] = {0.f, 0.f, 0.f, 0.f};
        for (int s = 0; s < 8; s++) {
            const int koff = s << 3;
            uint32_t a[4];
            const uint32_t addr = ydb + (mt*16 + (lane & 15)) * 272
                                + (((s << 4) + ((lane >> 4) << 3)) << 1);
            ldsm_x4(a[0], a[1], a[2], a[3], addr);
            const uint32_t b0 = Whp[(koff + t)*24 + nh*8 + g];
            const uint32_t bv = Whp[(koff + 4 + t)*24 + nh*8 + g];
            mma_bf16(ah, a, b0, bv);
        }
        const int r = mt*16 + g;
        const int c = nh*8 + 2*t;
        const float* bp = nh ? lvb : mub;
        const float bx = __ldg(bp + 2*t), by = __ldg(bp + 2*t + 1);
        Yh[r*20 + c]         = ah[0] + bx;
        Yh[r*20 + c + 1]     = ah[1] + by;
        Yh[(r+8)*20 + c]     = ah[2] + bx;
        Yh[(r+8)*20 + c + 1] = ah[3] + by;
    }
    __syncthreads();

    // ---- loss: thread = (node r = tid>>2, k-pair kg = tid&3) ----
    {
        const int r  = tid >> 2;
        const int kg = tid & 3;
        const int n  = base + r;
        const bool valid = (n < N_NODES);
        float part = 0.f;
        int op = 0;
        if (valid) {
            op = __ldg(op_id + n);
            const float4 muA = *(const float4*)(Yh + r*20);
            const float4 muB = *(const float4*)(Yh + r*20 + 4);
            const float4 lvA = *(const float4*)(Yh + r*20 + 8);
            const float4 lvB = *(const float4*)(Yh + r*20 + 12);
            const float muv[8] = { muA.x, muA.y, muA.z, muA.w, muB.x, muB.y, muB.z, muB.w };
            const float lvv[8] = { lvA.x, lvA.y, lvA.z, lvA.w, lvB.x, lvB.y, lvB.z, lvB.w };
            const float* wrow = opw + (size_t)op * (2 * LDIM * LDIM);
            float mpA = 0.f, mpB = 0.f, lpA = 0.f, lpB = 0.f;
            #pragma unroll
            for (int l = 0; l < LDIM; l++) {
                const float2 wm = __ldg((const float2*)(wrow + l*2*LDIM + 2*kg));
                const float2 wl = __ldg((const float2*)(wrow + l*2*LDIM + LDIM + 2*kg));
                mpA += muv[l] * wm.x; mpB += muv[l] * wm.y;
                lpA += lvv[l] * wl.x; lpB += lvv[l] * wl.y;
            }
            const float2 lab = __ldg((const float2*)(lat + (size_t)n*LDIM + 2*kg));
            const float dA = mpA - lab.x, dB = mpB - lab.y;
            part = dA*dA / (2.f*fexp(lpA) + 1e-7f) + 0.5f*lpA
                 + dB*dB / (2.f*fexp(lpB) + 1e-7f) + 0.5f*lpB;
        }
        part += __shfl_xor_sync(0xffffffffu, part, 1);
        part += __shfl_xor_sync(0xffffffffu, part, 2);
        const float lossn = part * (1.f / LDIM);
        if (valid && kg == 0) {
            atomicAdd(op_loss + op, lossn);
            atomicAdd(op_cnt  + op, 1.f);
        }
        float wval = (valid && kg == 0) ? lossn : 0.f;
        wval += __shfl_xor_sync(0xffffffffu, wval, 4);
        wval += __shfl_xor_sync(0xffffffffu, wval, 8);
        wval += __shfl_xor_sync(0xffffffffu, wval, 16);
        if (lane == 0) sL[w] = wval;
    }
    __syncthreads();
    if (tid == 0) {
        double s = 0.0;
        #pragma unroll
        for (int i = 0; i < 8; i++) s += (double)sL[i];
        atomicAdd(&g_lat_sum, s);
    }
}

// ----------------------------------------------------------------------------
// Kernel 4: finalize
// ----------------------------------------------------------------------------
__global__ void fin_kernel(float* __restrict__ out)
{
    if (threadIdx.x == 0) {
        const double lat_loss = g_lat_sum / (double)N_NODES;
        const double kl = -0.5 * (g_kl_sum / ((double)N_NODES * (double)FDIM));
        out[0] = (float)(lat_loss + kl);
    }
}

// ----------------------------------------------------------------------------
extern "C" void kernel_launch(void* const* d_in, const int* in_sizes, int n_in,
                              void* d_out, int out_size)
{
    const int*   op_id = (const int*)  d_in[0];
    const int*   sv_id = (const int*)  d_in[1];
    const int*   st_id = (const int*)  d_in[2];
    const float* lat   = (const float*)d_in[3];
    const int*   esrc  = (const int*)  d_in[4];
    const int*   edst  = (const int*)  d_in[5];
    const float* eps   = (const float*)d_in[6];
    const float* opE   = (const float*)d_in[7];
    const float* svE   = (const float*)d_in[8];
    const float* stE   = (const float*)d_in[9];
    const float* W1    = (const float*)d_in[10];
    const float* b1    = (const float*)d_in[11];
    const float* W2    = (const float*)d_in[12];
    const float* b2    = (const float*)d_in[13];
    const float* Wself = (const float*)d_in[14];
    const float* Wagg  = (const float*)d_in[15];
    const float* muW   = (const float*)d_in[16];
    const float* mub   = (const float*)d_in[17];
    const float* lvW   = (const float*)d_in[18];
    const float* lvb   = (const float*)d_in[19];
    const float* opw   = (const float*)d_in[20];

    float* out     = (float*)d_out;
    float* op_loss = out + 1;
    float* op_cnt  = out + 1 + OPC;

    const int ENC_SMEM = 84992;
    const int DEC_SMEM = 68608;
    static bool attr_done = false;
    if (!attr_done) {
        cudaFuncSetAttribute(enc_kernel, cudaFuncAttributeMaxDynamicSharedMemorySize, ENC_SMEM);
        cudaFuncSetAttribute(dec_kernel, cudaFuncAttributeMaxDynamicSharedMemorySize, DEC_SMEM);
        attr_done = true;
    }

    const int n_tiles = (N_NODES + TILE - 1) / TILE;   // 7813

    prep_kernel<<<1073, 256>>>(out, W1, W2, Wself, Wagg, muW, lvW,
                               opE, svE, stE);

    enc_kernel<<<n_tiles, 256, ENC_SMEM>>>(op_id, sv_id, st_id, lat, eps, b1, b2);

    scatter_kernel<<<15625, 256>>>(esrc, edst);

    dec_kernel<<<n_tiles, 256, DEC_SMEM>>>(op_id, lat, mub, lvb, opw,
                                           op_loss, op_cnt);

    fin_kernel<<<1, 32>>>(out);
}